// round 7
// baseline (speedup 1.0000x reference)
#include <cuda_runtime.h>
#include <cuda_bf16.h>
#include <math.h>
#include <stdint.h>

#define N_NODESC 50000
#define N_EDGESC 800000
#define CCH      128
#define N_GRAPHS 512
#define N_OUTC   5
#define BKT_CAP  96
#define PAD      136   // bf16 elements per SMEM row (conflict-free ldmatrix)
#define BM       64    // rows per GEMM CTA

// ---------------- scratch (device globals: allocation-free) ----------------
__device__ __align__(128) float g_h [N_NODESC * CCH];   // h = x + aggr
__device__ __align__(128) float g_h1[N_NODESC * CCH];   // after first linear
__device__ __align__(128) float g_xo[N_NODESC * CCH];   // layer output
__device__ __align__(128) float g_stats [2 * CCH];      // col sums / sumsq
__device__ __align__(128) float g_affine[2 * CCH];      // BN scale / shift
__device__ __align__(128) float g_pool[N_GRAPHS * CCH]; // max pool
__device__ __align__(128) int   g_deg[N_NODESC];        // in-degree / cursor
__device__ __align__(128) int2  g_bucket[N_NODESC * BKT_CAP]; // (src, w-bits)
__device__ __align__(128) __nv_bfloat16 g_wh[4 * CCH * CCH];  // weight hi
__device__ __align__(128) __nv_bfloat16 g_wl[4 * CCH * CCH];  // weight lo

// ---------------- PTX helpers ------------------------------------------------
__device__ __forceinline__ uint32_t smem_u32(const void* p) {
    uint32_t a;
    asm("{ .reg .u64 t; cvta.to.shared.u64 t, %1; cvt.u32.u64 %0, t; }"
        : "=r"(a) : "l"(p));
    return a;
}
__device__ __forceinline__ void ldmx4(uint32_t* r, uint32_t a) {
    asm volatile("ldmatrix.sync.aligned.m8n8.x4.shared.b16 {%0,%1,%2,%3}, [%4];"
                 : "=r"(r[0]), "=r"(r[1]), "=r"(r[2]), "=r"(r[3]) : "r"(a));
}
__device__ __forceinline__ void ldmx2(uint32_t* r, uint32_t a) {
    asm volatile("ldmatrix.sync.aligned.m8n8.x2.shared.b16 {%0,%1}, [%2];"
                 : "=r"(r[0]), "=r"(r[1]) : "r"(a));
}
__device__ __forceinline__ void mma16816(float* d, const uint32_t* a, const uint32_t* b) {
    asm volatile("mma.sync.aligned.m16n8k16.row.col.f32.bf16.bf16.f32 "
                 "{%0,%1,%2,%3}, {%4,%5,%6,%7}, {%8,%9}, {%0,%1,%2,%3};"
                 : "+f"(d[0]), "+f"(d[1]), "+f"(d[2]), "+f"(d[3])
                 : "r"(a[0]), "r"(a[1]), "r"(a[2]), "r"(a[3]), "r"(b[0]), "r"(b[1]));
}
__device__ __forceinline__ uint32_t pk_hi(float x, float y, uint32_t& lo_out) {
    __nv_bfloat16 hx = __float2bfloat16(x);
    __nv_bfloat16 hy = __float2bfloat16(y);
    __nv_bfloat16 lx = __float2bfloat16(x - __bfloat162float(hx));
    __nv_bfloat16 ly = __float2bfloat16(y - __bfloat162float(hy));
    lo_out = (uint32_t)__bfloat16_as_ushort(lx) |
             ((uint32_t)__bfloat16_as_ushort(ly) << 16);
    return (uint32_t)__bfloat16_as_ushort(hx) |
           ((uint32_t)__bfloat16_as_ushort(hy) << 16);
}

// ---------------- setup helpers ----------------
__global__ void zero_small_kernel() {
    int i = blockIdx.x * blockDim.x + threadIdx.x;
    if (i < N_GRAPHS * CCH) g_pool[i] = 0.f;
    if (i < N_NODESC) g_deg[i] = 0;
}
__global__ void zero_stats_kernel() {
    g_stats[threadIdx.x] = 0.f;          // 256 threads cover 2*CCH
}

// ---------------- weight pre-split: 4 x [128,128] fp32 -> bf16 hi/lo --------
__global__ void wsplit_kernel(const float* __restrict__ Wa,
                              const float* __restrict__ Wb,
                              const float* __restrict__ Wc,
                              const float* __restrict__ Wd) {
    int i = blockIdx.x * 256 + threadIdx.x;       // 0..65535
    int w = i >> 14;
    int e = i & 16383;
    const float* src = (w == 0) ? Wa : (w == 1) ? Wb : (w == 2) ? Wc : Wd;
    float v = src[e];
    __nv_bfloat16 h = __float2bfloat16(v);
    __nv_bfloat16 l = __float2bfloat16(v - __bfloat162float(h));
    g_wh[i] = h;
    g_wl[i] = l;
}

// ---------------- bucket build: per-dst list of (src, weight) ---------------
__global__ void bucket_build_kernel(const int* __restrict__ ei,
                                    const float* __restrict__ ew) {
    int e = blockIdx.x * blockDim.x + threadIdx.x;
    if (e >= N_EDGESC) return;
    int s = ei[e];
    int d = ei[N_EDGESC + e];
    float w = ew[e];
    int p = atomicAdd(&g_deg[d], 1);
    g_bucket[(size_t)d * BKT_CAP + p] = make_int2(s, __float_as_int(w));
}

// ---------------- aggregation: h[n] = x[n] + sum_e relu(x[src]+w*We+be) -----
// one warp per node; 2-way unrolled edge loop for memory-level parallelism
__global__ void __launch_bounds__(256)
node_agg_kernel(const float* __restrict__ x,
                const float* __restrict__ We,
                const float* __restrict__ be,
                float* __restrict__ h) {
    __shared__ float sWe[CCH];
    __shared__ float sbe[CCH];
    int t = threadIdx.x;
    if (t < CCH) sWe[t] = We[t];
    else         sbe[t - CCH] = be[t - CCH];
    __syncthreads();

    int warp = t >> 5;
    int lane = t & 31;
    int node = blockIdx.x * 8 + warp;
    if (node >= N_NODESC) return;

    int c = lane * 4;
    float w0 = sWe[c + 0], w1 = sWe[c + 1], w2 = sWe[c + 2], w3 = sWe[c + 3];
    float e0 = sbe[c + 0], e1 = sbe[c + 1], e2 = sbe[c + 2], e3 = sbe[c + 3];

    float4 acc = *(const float4*)(x + (size_t)node * CCH + c);  // self term
    float4 ac2 = make_float4(0.f, 0.f, 0.f, 0.f);

    int deg = __ldg(&g_deg[node]);
    const int2* bk = g_bucket + (size_t)node * BKT_CAP;

    int j = 0;
    for (; j + 2 <= deg; j += 2) {
        int2 p0 = __ldg(bk + j);
        int2 p1 = __ldg(bk + j + 1);
        float wa = __int_as_float(p0.y);
        float wb = __int_as_float(p1.y);
        float4 xa = *(const float4*)(x + (size_t)p0.x * CCH + c);
        float4 xb = *(const float4*)(x + (size_t)p1.x * CCH + c);
        acc.x += fmaxf(fmaf(wa, w0, xa.x) + e0, 0.f);
        ac2.x += fmaxf(fmaf(wb, w0, xb.x) + e0, 0.f);
        acc.y += fmaxf(fmaf(wa, w1, xa.y) + e1, 0.f);
        ac2.y += fmaxf(fmaf(wb, w1, xb.y) + e1, 0.f);
        acc.z += fmaxf(fmaf(wa, w2, xa.z) + e2, 0.f);
        ac2.z += fmaxf(fmaf(wb, w2, xb.z) + e2, 0.f);
        acc.w += fmaxf(fmaf(wa, w3, xa.w) + e3, 0.f);
        ac2.w += fmaxf(fmaf(wb, w3, xb.w) + e3, 0.f);
    }
    if (j < deg) {
        int2 p0 = __ldg(bk + j);
        float wa = __int_as_float(p0.y);
        float4 xa = *(const float4*)(x + (size_t)p0.x * CCH + c);
        acc.x += fmaxf(fmaf(wa, w0, xa.x) + e0, 0.f);
        acc.y += fmaxf(fmaf(wa, w1, xa.y) + e1, 0.f);
        acc.z += fmaxf(fmaf(wa, w2, xa.z) + e2, 0.f);
        acc.w += fmaxf(fmaf(wa, w3, xa.w) + e3, 0.f);
    }
    acc.x += ac2.x; acc.y += ac2.y; acc.z += ac2.z; acc.w += ac2.w;
    *(float4*)(h + (size_t)node * CCH + c) = acc;
}

// ---------------- HMMA GEMM: out = A' @ W^T + bias --------------------------
// bf16 3-pass split (AhBh + AhBl + AlBh). W pre-split in gmem (bf16 hi/lo).
// CTA: 64 rows x 128 cols, K=128 resident, 2 CTAs/SM.
// 8 warps (2 m-halves x 4 n-quarters), warp tile 32x32.
static constexpr int SMEM_GEMM =
    (2 * BM + 2 * CCH) * PAD * 2 + (3 * 128 + 256) * 4;   // 104448+2560 = 107008

template <bool AFF, bool RELU, bool STATS, bool POOL>
__global__ void __launch_bounds__(256, 2)
gemm_mma_kernel(const float* __restrict__ A,
                const __nv_bfloat16* __restrict__ Wh,
                const __nv_bfloat16* __restrict__ Wl,
                const float* __restrict__ bias, float* __restrict__ Cmat,
                const int* __restrict__ batch, int M) {
    extern __shared__ char smraw[];
    __nv_bfloat16* sAh = (__nv_bfloat16*)smraw;
    __nv_bfloat16* sAl = sAh + BM * PAD;
    __nv_bfloat16* sBh = sAl + BM * PAD;
    __nv_bfloat16* sBl = sBh + CCH * PAD;
    float* sBias  = (float*)(sBl + CCH * PAD);
    float* sSc    = sBias + 128;
    float* sSh    = sSc + 128;
    float* sStats = sSh + 128;

    int tid  = threadIdx.x;
    int wid  = tid >> 5;
    int lane = tid & 31;
    int wm   = wid & 1;        // 0..1 : 32-row half
    int wn   = wid >> 1;       // 0..3 : 32-col quarter
    int m0   = blockIdx.x * BM;

    if (tid < CCH) {
        sBias[tid] = bias[tid];
        if (AFF) {
            sSc[tid] = g_affine[tid];
            sSh[tid] = g_affine[CCH + tid];
        }
    }
    if (STATS && tid < 256) sStats[tid] = 0.f;
    __syncthreads();

    // ---- B tiles: straight bf16 copy from pre-split gmem (uint4 = 8 bf16) ----
    {
        const uint4* bh4 = (const uint4*)Wh;
        const uint4* bl4 = (const uint4*)Wl;
#pragma unroll
        for (int i = 0; i < 8; i++) {
            int idx = tid + i * 256;        // 0..2047 uint4 units
            int row = idx >> 4;
            int c8  = idx & 15;
            *(uint4*)(sBh + row * PAD + c8 * 8) = bh4[idx];
            *(uint4*)(sBl + row * PAD + c8 * 8) = bl4[idx];
        }
    }
    // ---- A tile: fp32 load + optional BN affine/ReLU + hi/lo split ----
    {
        int r  = tid >> 2;            // 0..63
        int ch = (tid & 3) * 32;      // col quarter
        bool valid = (m0 + r) < M;
        const float* arow = A + (size_t)(m0 + r) * CCH + ch;
        uint32_t abase = (uint32_t)(r * PAD + ch);
#pragma unroll
        for (int q = 0; q < 32; q += 4) {
            float4 v = valid ? *(const float4*)(arow + q)
                             : make_float4(0.f, 0.f, 0.f, 0.f);
            if (AFF) {
                int k = ch + q;
                v.x = fmaxf(fmaf(v.x, sSc[k + 0], sSh[k + 0]), 0.f);
                v.y = fmaxf(fmaf(v.y, sSc[k + 1], sSh[k + 1]), 0.f);
                v.z = fmaxf(fmaf(v.z, sSc[k + 2], sSh[k + 2]), 0.f);
                v.w = fmaxf(fmaf(v.w, sSc[k + 3], sSh[k + 3]), 0.f);
            }
            uint2 hi, lo;
            hi.x = pk_hi(v.x, v.y, lo.x);
            hi.y = pk_hi(v.z, v.w, lo.y);
            *(uint2*)(sAh + abase + q) = hi;
            *(uint2*)(sAl + abase + q) = lo;
        }
    }
    __syncthreads();

    int a_row = (lane & 7) + ((lane >> 3) & 1) * 8;
    int a_k   = (lane >> 4) * 8;
    int b_row = lane & 7;
    int b_k   = ((lane >> 3) & 1) * 8;

    uint32_t uAh = smem_u32(sAh), uAl = smem_u32(sAl);
    uint32_t uBh = smem_u32(sBh), uBl = smem_u32(sBl);

    float acc[2][4][4];
#pragma unroll
    for (int i = 0; i < 2; i++)
#pragma unroll
        for (int j = 0; j < 4; j++)
#pragma unroll
            for (int q = 0; q < 4; q++) acc[i][j][q] = 0.f;

    for (int k0 = 0; k0 < CCH; k0 += 16) {
        uint32_t ah[2][4], al[2][4], bh[4][2], bl[4][2];
#pragma unroll
        for (int mt = 0; mt < 2; mt++) {
            uint32_t off = (uint32_t)(((wm * 32 + mt * 16 + a_row) * PAD + k0 + a_k) * 2);
            ldmx4(ah[mt], uAh + off);
            ldmx4(al[mt], uAl + off);
        }
#pragma unroll
        for (int nt = 0; nt < 4; nt++) {
            uint32_t off = (uint32_t)(((wn * 32 + nt * 8 + b_row) * PAD + k0 + b_k) * 2);
            ldmx2(bh[nt], uBh + off);
            ldmx2(bl[nt], uBl + off);
        }
#pragma unroll
        for (int mt = 0; mt < 2; mt++)
#pragma unroll
            for (int nt = 0; nt < 4; nt++) {
                mma16816(acc[mt][nt], ah[mt], bh[nt]);
                mma16816(acc[mt][nt], ah[mt], bl[nt]);
                mma16816(acc[mt][nt], al[mt], bh[nt]);
            }
    }

    // ---- epilogue ----
    float sums[4][2], sqs[4][2];
    if (STATS) {
#pragma unroll
        for (int nt = 0; nt < 4; nt++) {
            sums[nt][0] = sums[nt][1] = 0.f;
            sqs[nt][0] = sqs[nt][1] = 0.f;
        }
    }

#pragma unroll
    for (int nt = 0; nt < 4; nt++) {
        int col = wn * 32 + nt * 8 + (lane & 3) * 2;
        float b0 = sBias[col], b1 = sBias[col + 1];
#pragma unroll
        for (int mt = 0; mt < 2; mt++) {
#pragma unroll
            for (int hf = 0; hf < 2; hf++) {
                int m = m0 + wm * 32 + mt * 16 + (lane >> 2) + hf * 8;
                if (m < M) {
                    float v0 = acc[mt][nt][hf * 2 + 0] + b0;
                    float v1 = acc[mt][nt][hf * 2 + 1] + b1;
                    if (RELU) { v0 = fmaxf(v0, 0.f); v1 = fmaxf(v1, 0.f); }
                    if (!POOL)
                        *(float2*)(Cmat + (size_t)m * CCH + col) = make_float2(v0, v1);
                    if (STATS) {
                        sums[nt][0] += v0; sums[nt][1] += v1;
                        sqs[nt][0] = fmaf(v0, v0, sqs[nt][0]);
                        sqs[nt][1] = fmaf(v1, v1, sqs[nt][1]);
                    }
                    if (POOL) {
                        int b = __ldg(batch + m);
                        int* prow = (int*)&g_pool[(size_t)b * CCH + col];
                        atomicMax(prow,     __float_as_int(v0));
                        atomicMax(prow + 1, __float_as_int(v1));
                    }
                }
            }
        }
    }

    if (STATS) {
#pragma unroll
        for (int nt = 0; nt < 4; nt++) {
            int col = wn * 32 + nt * 8 + (lane & 3) * 2;
            atomicAdd(&sStats[col],           sums[nt][0]);
            atomicAdd(&sStats[col + 1],       sums[nt][1]);
            atomicAdd(&sStats[128 + col],     sqs[nt][0]);
            atomicAdd(&sStats[128 + col + 1], sqs[nt][1]);
        }
        __syncthreads();
        if (tid < 256) atomicAdd(&g_stats[tid], sStats[tid]);
    }
}

// ---------------- BN finalize ------------------------------------------------
__global__ void bn_finalize_kernel(const float* __restrict__ g,
                                   const float* __restrict__ bt, float invN) {
    int c = threadIdx.x;
    float mu  = g_stats[c] * invN;
    float var = fmaf(-mu, mu, g_stats[CCH + c] * invN);
    float rs  = rsqrtf(var + 1e-5f);
    float sc  = g[c] * rs;
    g_affine[c]       = sc;
    g_affine[CCH + c] = fmaf(-mu, sc, bt[c]);
}

// ---------------- final linear [512,128] @ [5,128]^T + b --------------------
__global__ void final_linear_kernel(const float* __restrict__ lw,
                                    const float* __restrict__ lb,
                                    float* __restrict__ out) {
    int gph  = blockIdx.x;
    int o    = threadIdx.x >> 5;
    int lane = threadIdx.x & 31;
    const float* p    = g_pool + (size_t)gph * CCH;
    const float* wrow = lw + (size_t)o * CCH;
    float s = 0.f;
    for (int c = lane; c < CCH; c += 32) s = fmaf(p[c], wrow[c], s);
#pragma unroll
    for (int d = 16; d; d >>= 1) s += __shfl_xor_sync(0xffffffffu, s, d);
    if (lane == 0) out[gph * N_OUTC + o] = s + lb[o];
}

// ---------------- launch -----------------------------------------------------
extern "C" void kernel_launch(void* const* d_in, const int* in_sizes, int n_in,
                              void* d_out, int out_size) {
    const float* x   = (const float*)d_in[0];
    const int*   ei  = (const int*)  d_in[1];
    const float* ew  = (const float*)d_in[2];
    const int*   bat = (const int*)  d_in[3];
    const float* P[18];
    for (int i = 0; i < 18; i++) P[i] = (const float*)d_in[4 + i];
    // P: We0 be0 W1_0 b1_0 g0 bt0 W2_0 b2_0 | We1 be1 W1_1 b1_1 g1 bt1 W2_1 b2_1 | lin_w lin_b
    float* out = (float*)d_out;

    float *ph, *ph1, *pxo;
    __nv_bfloat16 *pwh, *pwl;
    cudaGetSymbolAddress((void**)&ph,  g_h);
    cudaGetSymbolAddress((void**)&ph1, g_h1);
    cudaGetSymbolAddress((void**)&pxo, g_xo);
    cudaGetSymbolAddress((void**)&pwh, g_wh);
    cudaGetSymbolAddress((void**)&pwl, g_wl);

    cudaFuncSetAttribute(gemm_mma_kernel<false, false, true, false>,
                         cudaFuncAttributeMaxDynamicSharedMemorySize, SMEM_GEMM);
    cudaFuncSetAttribute(gemm_mma_kernel<true, true, false, false>,
                         cudaFuncAttributeMaxDynamicSharedMemorySize, SMEM_GEMM);
    cudaFuncSetAttribute(gemm_mma_kernel<true, true, false, true>,
                         cudaFuncAttributeMaxDynamicSharedMemorySize, SMEM_GEMM);

    const int NBLK = (N_NODESC + BM - 1) / BM;
    const int AGG_BLK = (N_NODESC + 7) / 8;
    const float invN = 1.f / (float)N_NODESC;

    zero_small_kernel<<<(N_GRAPHS * CCH + 255) / 256, 256>>>();
    // pre-split weights: slot 0=W1_0, 1=W2_0, 2=W1_1, 3=W2_1
    wsplit_kernel<<<256, 256>>>(P[2], P[6], P[10], P[14]);
    bucket_build_kernel<<<(N_EDGESC + 255) / 256, 256>>>(ei, ew);

    const float* xin = x;
    for (int l = 0; l < 2; l++) {
        const float* We = P[l * 8 + 0];
        const float* be = P[l * 8 + 1];
        const float* b1 = P[l * 8 + 3];
        const float* gg = P[l * 8 + 4];
        const float* bt = P[l * 8 + 5];
        const float* b2 = P[l * 8 + 7];
        const __nv_bfloat16* W1h = pwh + (size_t)(l * 2 + 0) * CCH * CCH;
        const __nv_bfloat16* W1l = pwl + (size_t)(l * 2 + 0) * CCH * CCH;
        const __nv_bfloat16* W2h = pwh + (size_t)(l * 2 + 1) * CCH * CCH;
        const __nv_bfloat16* W2l = pwl + (size_t)(l * 2 + 1) * CCH * CCH;

        zero_stats_kernel<<<1, 256>>>();
        node_agg_kernel<<<AGG_BLK, 256>>>(xin, We, be, ph);
        gemm_mma_kernel<false, false, true, false>
            <<<NBLK, 256, SMEM_GEMM>>>(ph, W1h, W1l, b1, ph1, bat, N_NODESC);
        bn_finalize_kernel<<<1, 128>>>(gg, bt, invN);
        if (l == 0) {
            gemm_mma_kernel<true, true, false, false>
                <<<NBLK, 256, SMEM_GEMM>>>(ph1, W2h, W2l, b2, pxo, bat, N_NODESC);
        } else {
            gemm_mma_kernel<true, true, false, true>
                <<<NBLK, 256, SMEM_GEMM>>>(ph1, W2h, W2l, b2, pxo, bat, N_NODESC);
        }
        xin = pxo;
    }

    final_linear_kernel<<<N_GRAPHS, 160>>>(P[16], P[17], out);
}

// round 8
// speedup vs baseline: 1.0505x; 1.0505x over previous
#include <cuda_runtime.h>
#include <cuda_bf16.h>
#include <math.h>
#include <stdint.h>

#define N_NODESC 50000
#define N_EDGESC 800000
#define CCH      128
#define N_GRAPHS 512
#define N_OUTC   5
#define BKT_CAP  96
#define PAD      136   // bf16 elements per SMEM row (conflict-free ldmatrix)

// ---------------- scratch (device globals: allocation-free) ----------------
__device__ __align__(128) float g_h [N_NODESC * CCH];   // h = x + aggr
__device__ __align__(128) float g_h1[N_NODESC * CCH];   // after first linear
__device__ __align__(128) float g_xo[N_NODESC * CCH];   // layer output
__device__ __align__(128) float g_stats [2 * 2 * CCH];  // two slots: sums/sumsq
__device__ __align__(128) float g_pool[N_GRAPHS * CCH]; // max pool
__device__ __align__(128) int   g_deg[N_NODESC];        // in-degree / cursor
__device__ __align__(128) int2  g_bucket[N_NODESC * BKT_CAP]; // (src, w-bits)
__device__ __align__(128) __nv_bfloat16 g_wh[4 * CCH * CCH];  // weight hi
__device__ __align__(128) __nv_bfloat16 g_wl[4 * CCH * CCH];  // weight lo

// ---------------- PTX helpers ------------------------------------------------
__device__ __forceinline__ uint32_t smem_u32(const void* p) {
    uint32_t a;
    asm("{ .reg .u64 t; cvta.to.shared.u64 t, %1; cvt.u32.u64 %0, t; }"
        : "=r"(a) : "l"(p));
    return a;
}
__device__ __forceinline__ void ldmx4(uint32_t* r, uint32_t a) {
    asm volatile("ldmatrix.sync.aligned.m8n8.x4.shared.b16 {%0,%1,%2,%3}, [%4];"
                 : "=r"(r[0]), "=r"(r[1]), "=r"(r[2]), "=r"(r[3]) : "r"(a));
}
__device__ __forceinline__ void ldmx2(uint32_t* r, uint32_t a) {
    asm volatile("ldmatrix.sync.aligned.m8n8.x2.shared.b16 {%0,%1}, [%2];"
                 : "=r"(r[0]), "=r"(r[1]) : "r"(a));
}
__device__ __forceinline__ void mma16816(float* d, const uint32_t* a, const uint32_t* b) {
    asm volatile("mma.sync.aligned.m16n8k16.row.col.f32.bf16.bf16.f32 "
                 "{%0,%1,%2,%3}, {%4,%5,%6,%7}, {%8,%9}, {%0,%1,%2,%3};"
                 : "+f"(d[0]), "+f"(d[1]), "+f"(d[2]), "+f"(d[3])
                 : "r"(a[0]), "r"(a[1]), "r"(a[2]), "r"(a[3]), "r"(b[0]), "r"(b[1]));
}
__device__ __forceinline__ uint32_t pk_hi(float x, float y, uint32_t& lo_out) {
    __nv_bfloat16 hx = __float2bfloat16(x);
    __nv_bfloat16 hy = __float2bfloat16(y);
    __nv_bfloat16 lx = __float2bfloat16(x - __bfloat162float(hx));
    __nv_bfloat16 ly = __float2bfloat16(y - __bfloat162float(hy));
    lo_out = (uint32_t)__bfloat16_as_ushort(lx) |
             ((uint32_t)__bfloat16_as_ushort(ly) << 16);
    return (uint32_t)__bfloat16_as_ushort(hx) |
           ((uint32_t)__bfloat16_as_ushort(hy) << 16);
}

// ---------------- fused setup: zero pool/deg/stats + pre-split weights ------
__global__ void setup_kernel(const float* __restrict__ Wa,
                             const float* __restrict__ Wb,
                             const float* __restrict__ Wc,
                             const float* __restrict__ Wd) {
    int i = blockIdx.x * 256 + threadIdx.x;       // 0..65535
    if (i < N_GRAPHS * CCH) g_pool[i] = 0.f;
    if (i < N_NODESC) g_deg[i] = 0;
    if (i < 4 * CCH) g_stats[i] = 0.f;
    int w = i >> 14;
    int e = i & 16383;
    const float* src = (w == 0) ? Wa : (w == 1) ? Wb : (w == 2) ? Wc : Wd;
    float v = src[e];
    __nv_bfloat16 h = __float2bfloat16(v);
    __nv_bfloat16 l = __float2bfloat16(v - __bfloat162float(h));
    g_wh[i] = h;
    g_wl[i] = l;
}

// ---------------- bucket build: per-dst list of (src, weight) ---------------
__global__ void bucket_build_kernel(const int* __restrict__ ei,
                                    const float* __restrict__ ew) {
    int e = blockIdx.x * blockDim.x + threadIdx.x;
    if (e >= N_EDGESC) return;
    int s = ei[e];
    int d = ei[N_EDGESC + e];
    float w = ew[e];
    int p = atomicAdd(&g_deg[d], 1);
    g_bucket[(size_t)d * BKT_CAP + p] = make_int2(s, __float_as_int(w));
}

// ---------------- aggregation: h[n] = x[n] + sum_e relu(x[src]+w*We+be) -----
__global__ void __launch_bounds__(256)
node_agg_kernel(const float* __restrict__ x,
                const float* __restrict__ We,
                const float* __restrict__ be,
                float* __restrict__ h) {
    __shared__ float sWe[CCH];
    __shared__ float sbe[CCH];
    int t = threadIdx.x;
    if (t < CCH) sWe[t] = We[t];
    else         sbe[t - CCH] = be[t - CCH];
    __syncthreads();

    int warp = t >> 5;
    int lane = t & 31;
    int node = blockIdx.x * 8 + warp;
    if (node >= N_NODESC) return;

    int c = lane * 4;
    float w0 = sWe[c + 0], w1 = sWe[c + 1], w2 = sWe[c + 2], w3 = sWe[c + 3];
    float e0 = sbe[c + 0], e1 = sbe[c + 1], e2 = sbe[c + 2], e3 = sbe[c + 3];

    float4 acc = *(const float4*)(x + (size_t)node * CCH + c);  // self term
    float4 ac2 = make_float4(0.f, 0.f, 0.f, 0.f);

    int deg = __ldg(&g_deg[node]);
    const int2* bk = g_bucket + (size_t)node * BKT_CAP;

    int j = 0;
    for (; j + 2 <= deg; j += 2) {
        int2 p0 = __ldg(bk + j);
        int2 p1 = __ldg(bk + j + 1);
        float wa = __int_as_float(p0.y);
        float wb = __int_as_float(p1.y);
        float4 xa = *(const float4*)(x + (size_t)p0.x * CCH + c);
        float4 xb = *(const float4*)(x + (size_t)p1.x * CCH + c);
        acc.x += fmaxf(fmaf(wa, w0, xa.x) + e0, 0.f);
        ac2.x += fmaxf(fmaf(wb, w0, xb.x) + e0, 0.f);
        acc.y += fmaxf(fmaf(wa, w1, xa.y) + e1, 0.f);
        ac2.y += fmaxf(fmaf(wb, w1, xb.y) + e1, 0.f);
        acc.z += fmaxf(fmaf(wa, w2, xa.z) + e2, 0.f);
        ac2.z += fmaxf(fmaf(wb, w2, xb.z) + e2, 0.f);
        acc.w += fmaxf(fmaf(wa, w3, xa.w) + e3, 0.f);
        ac2.w += fmaxf(fmaf(wb, w3, xb.w) + e3, 0.f);
    }
    if (j < deg) {
        int2 p0 = __ldg(bk + j);
        float wa = __int_as_float(p0.y);
        float4 xa = *(const float4*)(x + (size_t)p0.x * CCH + c);
        acc.x += fmaxf(fmaf(wa, w0, xa.x) + e0, 0.f);
        acc.y += fmaxf(fmaf(wa, w1, xa.y) + e1, 0.f);
        acc.z += fmaxf(fmaf(wa, w2, xa.z) + e2, 0.f);
        acc.w += fmaxf(fmaf(wa, w3, xa.w) + e3, 0.f);
    }
    acc.x += ac2.x; acc.y += ac2.y; acc.z += ac2.z; acc.w += ac2.w;
    *(float4*)(h + (size_t)node * CCH + c) = acc;
}

// ---------------- HMMA GEMM: out = A' @ W^T + bias --------------------------
// bf16 3-pass split (AhBh + AhBl + AlBh). W pre-split in gmem (bf16 hi/lo).
// A' = A (AFF=false) or relu(A*scale+shift) with BN affine computed IN-KERNEL
// from stats[] (fused bn_finalize). out = relu if RELU.
// STATS: column sum/sumsq -> stats_out. POOL: atomicMax -> g_pool, no store.
// CTA: 128 rows x 128 cols, K=128 resident. 8 warps (2m x 4n), warp 64x32.
static constexpr int SMEM_GEMM =
    4 * 128 * PAD * 2 + (3 * 128 + 256) * 4;   // 141824

template <bool AFF, bool RELU, bool STATS, bool POOL>
__global__ void __launch_bounds__(256, 1)
gemm_mma_kernel(const float* __restrict__ A,
                const __nv_bfloat16* __restrict__ Wh,
                const __nv_bfloat16* __restrict__ Wl,
                const float* __restrict__ bias,
                const float* __restrict__ stats_in,   // AFF: slot with sums/sumsq
                const float* __restrict__ gg,
                const float* __restrict__ bt,
                float* __restrict__ stats_out,        // STATS: slot to accumulate
                float* __restrict__ Cmat,
                const int* __restrict__ batch, int M) {
    extern __shared__ char smraw[];
    __nv_bfloat16* sAh = (__nv_bfloat16*)smraw;
    __nv_bfloat16* sAl = sAh + 128 * PAD;
    __nv_bfloat16* sBh = sAl + 128 * PAD;
    __nv_bfloat16* sBl = sBh + 128 * PAD;
    float* sBias  = (float*)(sBl + 128 * PAD);
    float* sSc    = sBias + 128;
    float* sSh    = sSc + 128;
    float* sStats = sSh + 128;

    int tid  = threadIdx.x;
    int wid  = tid >> 5;
    int lane = tid & 31;
    int wm   = wid & 1;        // 0..1 : 64-row half
    int wn   = wid >> 1;       // 0..3 : 32-col quarter
    int m0   = blockIdx.x * 128;

    if (tid < CCH) {
        sBias[tid] = bias[tid];
        if (AFF) {
            // fused bn_finalize: affine from stats slot
            const float invN = 1.f / (float)N_NODESC;
            float mu  = stats_in[tid] * invN;
            float var = fmaf(-mu, mu, stats_in[CCH + tid] * invN);
            float rs  = rsqrtf(var + 1e-5f);
            float sc  = gg[tid] * rs;
            sSc[tid] = sc;
            sSh[tid] = fmaf(-mu, sc, bt[tid]);
        }
    }
    if (STATS && tid < 256) sStats[tid] = 0.f;
    __syncthreads();

    // ---- B tiles: straight bf16 copy from pre-split gmem (uint4 = 8 bf16) ----
    {
        const uint4* bh4 = (const uint4*)Wh;
        const uint4* bl4 = (const uint4*)Wl;
#pragma unroll
        for (int i = 0; i < 8; i++) {
            int idx = tid + i * 256;        // 0..2047 uint4 units
            int row = idx >> 4;
            int c8  = idx & 15;
            *(uint4*)(sBh + row * PAD + c8 * 8) = bh4[idx];
            *(uint4*)(sBl + row * PAD + c8 * 8) = bl4[idx];
        }
    }
    // ---- A tile: fp32 load + optional BN affine/ReLU + hi/lo split ----
    {
        int r  = tid >> 1;            // 0..127
        int ch = (tid & 1) * 64;      // col half
        bool valid = (m0 + r) < M;
        const float* arow = A + (size_t)(m0 + r) * CCH + ch;
        uint32_t abase = (uint32_t)(r * PAD + ch);
#pragma unroll
        for (int q = 0; q < 64; q += 4) {
            float4 v = valid ? *(const float4*)(arow + q)
                             : make_float4(0.f, 0.f, 0.f, 0.f);
            if (AFF) {
                int k = ch + q;
                v.x = fmaxf(fmaf(v.x, sSc[k + 0], sSh[k + 0]), 0.f);
                v.y = fmaxf(fmaf(v.y, sSc[k + 1], sSh[k + 1]), 0.f);
                v.z = fmaxf(fmaf(v.z, sSc[k + 2], sSh[k + 2]), 0.f);
                v.w = fmaxf(fmaf(v.w, sSc[k + 3], sSh[k + 3]), 0.f);
            }
            uint2 hi, lo;
            hi.x = pk_hi(v.x, v.y, lo.x);
            hi.y = pk_hi(v.z, v.w, lo.y);
            *(uint2*)(sAh + abase + q) = hi;
            *(uint2*)(sAl + abase + q) = lo;
        }
    }
    __syncthreads();

    int a_row = (lane & 7) + ((lane >> 3) & 1) * 8;
    int a_k   = (lane >> 4) * 8;
    int b_row = lane & 7;
    int b_k   = ((lane >> 3) & 1) * 8;

    uint32_t uAh = smem_u32(sAh), uAl = smem_u32(sAl);
    uint32_t uBh = smem_u32(sBh), uBl = smem_u32(sBl);

    float acc[4][4][4];
#pragma unroll
    for (int i = 0; i < 4; i++)
#pragma unroll
        for (int j = 0; j < 4; j++)
#pragma unroll
            for (int q = 0; q < 4; q++) acc[i][j][q] = 0.f;

    for (int k0 = 0; k0 < CCH; k0 += 16) {
        uint32_t ah[4][4], al[4][4], bh[4][2], bl[4][2];
#pragma unroll
        for (int mt = 0; mt < 4; mt++) {
            uint32_t off = (uint32_t)(((wm * 64 + mt * 16 + a_row) * PAD + k0 + a_k) * 2);
            ldmx4(ah[mt], uAh + off);
            ldmx4(al[mt], uAl + off);
        }
#pragma unroll
        for (int nt = 0; nt < 4; nt++) {
            uint32_t off = (uint32_t)(((wn * 32 + nt * 8 + b_row) * PAD + k0 + b_k) * 2);
            ldmx2(bh[nt], uBh + off);
            ldmx2(bl[nt], uBl + off);
        }
#pragma unroll
        for (int mt = 0; mt < 4; mt++)
#pragma unroll
            for (int nt = 0; nt < 4; nt++) {
                mma16816(acc[mt][nt], ah[mt], bh[nt]);
                mma16816(acc[mt][nt], ah[mt], bl[nt]);
                mma16816(acc[mt][nt], al[mt], bh[nt]);
            }
    }

    // ---- epilogue ----
    float sums[4][2], sqs[4][2];
    if (STATS) {
#pragma unroll
        for (int nt = 0; nt < 4; nt++) {
            sums[nt][0] = sums[nt][1] = 0.f;
            sqs[nt][0] = sqs[nt][1] = 0.f;
        }
    }

#pragma unroll
    for (int nt = 0; nt < 4; nt++) {
        int col = wn * 32 + nt * 8 + (lane & 3) * 2;
        float b0 = sBias[col], b1 = sBias[col + 1];
#pragma unroll
        for (int mt = 0; mt < 4; mt++) {
#pragma unroll
            for (int hf = 0; hf < 2; hf++) {
                int m = m0 + wm * 64 + mt * 16 + (lane >> 2) + hf * 8;
                if (m < M) {
                    float v0 = acc[mt][nt][hf * 2 + 0] + b0;
                    float v1 = acc[mt][nt][hf * 2 + 1] + b1;
                    if (RELU) { v0 = fmaxf(v0, 0.f); v1 = fmaxf(v1, 0.f); }
                    if (!POOL)
                        *(float2*)(Cmat + (size_t)m * CCH + col) = make_float2(v0, v1);
                    if (STATS) {
                        sums[nt][0] += v0; sums[nt][1] += v1;
                        sqs[nt][0] = fmaf(v0, v0, sqs[nt][0]);
                        sqs[nt][1] = fmaf(v1, v1, sqs[nt][1]);
                    }
                    if (POOL) {
                        int b = __ldg(batch + m);
                        int* prow = (int*)&g_pool[(size_t)b * CCH + col];
                        atomicMax(prow,     __float_as_int(v0));
                        atomicMax(prow + 1, __float_as_int(v1));
                    }
                }
            }
        }
    }

    if (STATS) {
#pragma unroll
        for (int nt = 0; nt < 4; nt++) {
            int col = wn * 32 + nt * 8 + (lane & 3) * 2;
            atomicAdd(&sStats[col],           sums[nt][0]);
            atomicAdd(&sStats[col + 1],       sums[nt][1]);
            atomicAdd(&sStats[128 + col],     sqs[nt][0]);
            atomicAdd(&sStats[128 + col + 1], sqs[nt][1]);
        }
        __syncthreads();
        if (tid < 256) atomicAdd(&stats_out[tid], sStats[tid]);
    }
}

// ---------------- final linear [512,128] @ [5,128]^T + b --------------------
__global__ void final_linear_kernel(const float* __restrict__ lw,
                                    const float* __restrict__ lb,
                                    float* __restrict__ out) {
    int gph  = blockIdx.x;
    int o    = threadIdx.x >> 5;
    int lane = threadIdx.x & 31;
    const float* p    = g_pool + (size_t)gph * CCH;
    const float* wrow = lw + (size_t)o * CCH;
    float s = 0.f;
    for (int c = lane; c < CCH; c += 32) s = fmaf(p[c], wrow[c], s);
#pragma unroll
    for (int d = 16; d; d >>= 1) s += __shfl_xor_sync(0xffffffffu, s, d);
    if (lane == 0) out[gph * N_OUTC + o] = s + lb[o];
}

// ---------------- launch -----------------------------------------------------
extern "C" void kernel_launch(void* const* d_in, const int* in_sizes, int n_in,
                              void* d_out, int out_size) {
    const float* x   = (const float*)d_in[0];
    const int*   ei  = (const int*)  d_in[1];
    const float* ew  = (const float*)d_in[2];
    const int*   bat = (const int*)  d_in[3];
    const float* P[18];
    for (int i = 0; i < 18; i++) P[i] = (const float*)d_in[4 + i];
    // P: We0 be0 W1_0 b1_0 g0 bt0 W2_0 b2_0 | We1 be1 W1_1 b1_1 g1 bt1 W2_1 b2_1 | lin_w lin_b
    float* out = (float*)d_out;

    float *ph, *ph1, *pxo, *pst;
    __nv_bfloat16 *pwh, *pwl;
    cudaGetSymbolAddress((void**)&ph,  g_h);
    cudaGetSymbolAddress((void**)&ph1, g_h1);
    cudaGetSymbolAddress((void**)&pxo, g_xo);
    cudaGetSymbolAddress((void**)&pst, g_stats);
    cudaGetSymbolAddress((void**)&pwh, g_wh);
    cudaGetSymbolAddress((void**)&pwl, g_wl);

    cudaFuncSetAttribute(gemm_mma_kernel<false, false, true, false>,
                         cudaFuncAttributeMaxDynamicSharedMemorySize, SMEM_GEMM);
    cudaFuncSetAttribute(gemm_mma_kernel<true, true, false, false>,
                         cudaFuncAttributeMaxDynamicSharedMemorySize, SMEM_GEMM);
    cudaFuncSetAttribute(gemm_mma_kernel<true, true, false, true>,
                         cudaFuncAttributeMaxDynamicSharedMemorySize, SMEM_GEMM);

    const int NBLK = (N_NODESC + 127) / 128;
    const int AGG_BLK = (N_NODESC + 7) / 8;

    // fused setup: zeros + weight pre-split (slots 0=W1_0,1=W2_0,2=W1_1,3=W2_1)
    setup_kernel<<<256, 256>>>(P[2], P[6], P[10], P[14]);
    bucket_build_kernel<<<(N_EDGESC + 255) / 256, 256>>>(ei, ew);

    const float* xin = x;
    for (int l = 0; l < 2; l++) {
        const float* We = P[l * 8 + 0];
        const float* be = P[l * 8 + 1];
        const float* b1 = P[l * 8 + 3];
        const float* gg = P[l * 8 + 4];
        const float* bt = P[l * 8 + 5];
        const float* b2 = P[l * 8 + 7];
        const __nv_bfloat16* W1h = pwh + (size_t)(l * 2 + 0) * CCH * CCH;
        const __nv_bfloat16* W1l = pwl + (size_t)(l * 2 + 0) * CCH * CCH;
        const __nv_bfloat16* W2h = pwh + (size_t)(l * 2 + 1) * CCH * CCH;
        const __nv_bfloat16* W2l = pwl + (size_t)(l * 2 + 1) * CCH * CCH;
        float* slot = pst + (size_t)l * 2 * CCH;

        node_agg_kernel<<<AGG_BLK, 256>>>(xin, We, be, ph);
        // h1 = h @ W1^T + b1, fused BN stats -> slot
        gemm_mma_kernel<false, false, true, false><<<NBLK, 256, SMEM_GEMM>>>(
            ph, W1h, W1l, b1, nullptr, nullptr, nullptr, slot, ph1, bat, N_NODESC);
        // x_out = relu( relu(BN(h1)) @ W2^T + b2 ), BN affine fused from slot
        if (l == 0) {
            gemm_mma_kernel<true, true, false, false><<<NBLK, 256, SMEM_GEMM>>>(
                ph1, W2h, W2l, b2, slot, gg, bt, nullptr, pxo, bat, N_NODESC);
        } else {
            gemm_mma_kernel<true, true, false, true><<<NBLK, 256, SMEM_GEMM>>>(
                ph1, W2h, W2l, b2, slot, gg, bt, nullptr, pxo, bat, N_NODESC);
        }
        xin = pxo;
    }

    final_linear_kernel<<<N_GRAPHS, 160>>>(P[16], P[17], out);
}

// round 9
// speedup vs baseline: 1.1034x; 1.0504x over previous
#include <cuda_runtime.h>
#include <cuda_bf16.h>
#include <math.h>
#include <stdint.h>

#define N_NODESC 50000
#define N_PADROW 50048   // 391 * 128, slack rows for guard-free GEMM prologue
#define N_EDGESC 800000
#define CCH      128
#define N_GRAPHS 512
#define N_OUTC   5
#define BKT_CAP  96
#define PAD      136   // bf16 elements per SMEM row (conflict-free ldmatrix)

// ---------------- scratch (device globals: allocation-free) ----------------
__device__ __align__(128) __nv_bfloat16 g_hh[N_PADROW * CCH];  // h hi (bf16)
__device__ __align__(128) __nv_bfloat16 g_hl[N_PADROW * CCH];  // h lo (bf16)
__device__ __align__(128) float g_h1[N_NODESC * CCH];   // after first linear
__device__ __align__(128) float g_xo[N_NODESC * CCH];   // layer output
__device__ __align__(128) float g_stats [2 * 2 * CCH];  // two slots: sums/sumsq
__device__ __align__(128) float g_pool[N_GRAPHS * CCH]; // max pool
__device__ __align__(128) int   g_deg[N_NODESC];        // in-degree / cursor
__device__ __align__(128) int2  g_bucket[N_NODESC * BKT_CAP]; // (src, w-bits)
__device__ __align__(128) __nv_bfloat16 g_wh[4 * CCH * CCH];  // weight hi
__device__ __align__(128) __nv_bfloat16 g_wl[4 * CCH * CCH];  // weight lo

// ---------------- PTX helpers ------------------------------------------------
__device__ __forceinline__ uint32_t smem_u32(const void* p) {
    uint32_t a;
    asm("{ .reg .u64 t; cvta.to.shared.u64 t, %1; cvt.u32.u64 %0, t; }"
        : "=r"(a) : "l"(p));
    return a;
}
__device__ __forceinline__ void ldmx4(uint32_t* r, uint32_t a) {
    asm volatile("ldmatrix.sync.aligned.m8n8.x4.shared.b16 {%0,%1,%2,%3}, [%4];"
                 : "=r"(r[0]), "=r"(r[1]), "=r"(r[2]), "=r"(r[3]) : "r"(a));
}
__device__ __forceinline__ void ldmx2(uint32_t* r, uint32_t a) {
    asm volatile("ldmatrix.sync.aligned.m8n8.x2.shared.b16 {%0,%1}, [%2];"
                 : "=r"(r[0]), "=r"(r[1]) : "r"(a));
}
__device__ __forceinline__ void mma16816(float* d, const uint32_t* a, const uint32_t* b) {
    asm volatile("mma.sync.aligned.m16n8k16.row.col.f32.bf16.bf16.f32 "
                 "{%0,%1,%2,%3}, {%4,%5,%6,%7}, {%8,%9}, {%0,%1,%2,%3};"
                 : "+f"(d[0]), "+f"(d[1]), "+f"(d[2]), "+f"(d[3])
                 : "r"(a[0]), "r"(a[1]), "r"(a[2]), "r"(a[3]), "r"(b[0]), "r"(b[1]));
}
// accurate (round-nearest) split — used once for weights
__device__ __forceinline__ uint32_t pk_hi(float x, float y, uint32_t& lo_out) {
    __nv_bfloat16 hx = __float2bfloat16(x);
    __nv_bfloat16 hy = __float2bfloat16(y);
    __nv_bfloat16 lx = __float2bfloat16(x - __bfloat162float(hx));
    __nv_bfloat16 ly = __float2bfloat16(y - __bfloat162float(hy));
    lo_out = (uint32_t)__bfloat16_as_ushort(lx) |
             ((uint32_t)__bfloat16_as_ushort(ly) << 16);
    return (uint32_t)__bfloat16_as_ushort(hx) |
           ((uint32_t)__bfloat16_as_ushort(hy) << 16);
}
// fast truncation split: hi = top16(v), residual exact, lo = top16(residual)
__device__ __forceinline__ void fsplit2(float v0, float v1,
                                        uint32_t& hi, uint32_t& lo) {
    uint32_t u0 = __float_as_uint(v0), u1 = __float_as_uint(v1);
    hi = __byte_perm(u0, u1, 0x7632);
    float r0 = v0 - __uint_as_float(u0 & 0xFFFF0000u);
    float r1 = v1 - __uint_as_float(u1 & 0xFFFF0000u);
    lo = __byte_perm(__float_as_uint(r0), __float_as_uint(r1), 0x7632);
}

// ---------------- fused setup: zero pool/deg/stats + pre-split weights ------
__global__ void setup_kernel(const float* __restrict__ Wa,
                             const float* __restrict__ Wb,
                             const float* __restrict__ Wc,
                             const float* __restrict__ Wd) {
    int i = blockIdx.x * 256 + threadIdx.x;       // 0..65535
    if (i < N_GRAPHS * CCH) g_pool[i] = 0.f;
    if (i < N_NODESC) g_deg[i] = 0;
    if (i < 4 * CCH) g_stats[i] = 0.f;
    int w = i >> 14;
    int e = i & 16383;
    const float* src = (w == 0) ? Wa : (w == 1) ? Wb : (w == 2) ? Wc : Wd;
    float v = src[e];
    __nv_bfloat16 h = __float2bfloat16(v);
    __nv_bfloat16 l = __float2bfloat16(v - __bfloat162float(h));
    g_wh[i] = h;
    g_wl[i] = l;
}

// ---------------- bucket build: per-dst list of (src, weight) ---------------
__global__ void bucket_build_kernel(const int* __restrict__ ei,
                                    const float* __restrict__ ew) {
    int e = blockIdx.x * blockDim.x + threadIdx.x;
    if (e >= N_EDGESC) return;
    int s = ei[e];
    int d = ei[N_EDGESC + e];
    float w = ew[e];
    int p = atomicAdd(&g_deg[d], 1);
    g_bucket[(size_t)d * BKT_CAP + p] = make_int2(s, __float_as_int(w));
}

// ---------------- aggregation: h[n] = x[n] + sum_e relu(x[src]+w*We+be) -----
// output written directly as bf16 hi/lo split (feeds GEMM1 with zero convert)
__global__ void __launch_bounds__(256)
node_agg_kernel(const float* __restrict__ x,
                const float* __restrict__ We,
                const float* __restrict__ be,
                __nv_bfloat16* __restrict__ hh,
                __nv_bfloat16* __restrict__ hl) {
    __shared__ float sWe[CCH];
    __shared__ float sbe[CCH];
    int t = threadIdx.x;
    if (t < CCH) sWe[t] = We[t];
    else         sbe[t - CCH] = be[t - CCH];
    __syncthreads();

    int warp = t >> 5;
    int lane = t & 31;
    int node = blockIdx.x * 8 + warp;
    if (node >= N_NODESC) return;

    int c = lane * 4;
    float w0 = sWe[c + 0], w1 = sWe[c + 1], w2 = sWe[c + 2], w3 = sWe[c + 3];
    float e0 = sbe[c + 0], e1 = sbe[c + 1], e2 = sbe[c + 2], e3 = sbe[c + 3];

    float4 acc = *(const float4*)(x + (size_t)node * CCH + c);  // self term
    float4 ac2 = make_float4(0.f, 0.f, 0.f, 0.f);

    int deg = __ldg(&g_deg[node]);
    const int2* bk = g_bucket + (size_t)node * BKT_CAP;

    int j = 0;
    for (; j + 2 <= deg; j += 2) {
        int2 p0 = __ldg(bk + j);
        int2 p1 = __ldg(bk + j + 1);
        float wa = __int_as_float(p0.y);
        float wb = __int_as_float(p1.y);
        float4 xa = *(const float4*)(x + (size_t)p0.x * CCH + c);
        float4 xb = *(const float4*)(x + (size_t)p1.x * CCH + c);
        acc.x += fmaxf(fmaf(wa, w0, xa.x) + e0, 0.f);
        ac2.x += fmaxf(fmaf(wb, w0, xb.x) + e0, 0.f);
        acc.y += fmaxf(fmaf(wa, w1, xa.y) + e1, 0.f);
        ac2.y += fmaxf(fmaf(wb, w1, xb.y) + e1, 0.f);
        acc.z += fmaxf(fmaf(wa, w2, xa.z) + e2, 0.f);
        ac2.z += fmaxf(fmaf(wb, w2, xb.z) + e2, 0.f);
        acc.w += fmaxf(fmaf(wa, w3, xa.w) + e3, 0.f);
        ac2.w += fmaxf(fmaf(wb, w3, xb.w) + e3, 0.f);
    }
    if (j < deg) {
        int2 p0 = __ldg(bk + j);
        float wa = __int_as_float(p0.y);
        float4 xa = *(const float4*)(x + (size_t)p0.x * CCH + c);
        acc.x += fmaxf(fmaf(wa, w0, xa.x) + e0, 0.f);
        acc.y += fmaxf(fmaf(wa, w1, xa.y) + e1, 0.f);
        acc.z += fmaxf(fmaf(wa, w2, xa.z) + e2, 0.f);
        acc.w += fmaxf(fmaf(wa, w3, xa.w) + e3, 0.f);
    }
    acc.x += ac2.x; acc.y += ac2.y; acc.z += ac2.z; acc.w += ac2.w;

    uint2 hi, lo;
    fsplit2(acc.x, acc.y, hi.x, lo.x);
    fsplit2(acc.z, acc.w, hi.y, lo.y);
    *(uint2*)(hh + (size_t)node * CCH + c) = hi;
    *(uint2*)(hl + (size_t)node * CCH + c) = lo;
}

// ---------------- HMMA GEMM: out = A' @ W^T + bias --------------------------
// bf16 3-pass split (AhBh + AhBl + AlBh). W pre-split in gmem.
// ASPLIT: A pre-split in gmem (pure-copy prologue).
// !ASPLIT: A fp32 + BN affine (computed in-kernel from stats) + ReLU + fast split.
// STATS: column sum/sumsq -> stats_out. POOL: atomicMax -> g_pool, no store.
// CTA: 128 rows x 128 cols, K=128 resident. 8 warps (2m x 4n), warp 64x32.
static constexpr int SMEM_GEMM =
    4 * 128 * PAD * 2 + (3 * 128 + 256) * 4;   // 141824

template <bool ASPLIT, bool RELU, bool STATS, bool POOL>
__global__ void __launch_bounds__(256, 1)
gemm_mma_kernel(const float* __restrict__ A,
                const __nv_bfloat16* __restrict__ Ahg,
                const __nv_bfloat16* __restrict__ Alg,
                const __nv_bfloat16* __restrict__ Wh,
                const __nv_bfloat16* __restrict__ Wl,
                const float* __restrict__ bias,
                const float* __restrict__ stats_in,
                const float* __restrict__ gg,
                const float* __restrict__ bt,
                float* __restrict__ stats_out,
                float* __restrict__ Cmat,
                const int* __restrict__ batch, int M) {
    extern __shared__ char smraw[];
    __nv_bfloat16* sAh = (__nv_bfloat16*)smraw;
    __nv_bfloat16* sAl = sAh + 128 * PAD;
    __nv_bfloat16* sBh = sAl + 128 * PAD;
    __nv_bfloat16* sBl = sBh + 128 * PAD;
    float* sBias  = (float*)(sBl + 128 * PAD);
    float* sSc    = sBias + 128;
    float* sSh    = sSc + 128;
    float* sStats = sSh + 128;

    int tid  = threadIdx.x;
    int wid  = tid >> 5;
    int lane = tid & 31;
    int wm   = wid & 1;        // 0..1 : 64-row half
    int wn   = wid >> 1;       // 0..3 : 32-col quarter
    int m0   = blockIdx.x * 128;

    if (tid < CCH) {
        sBias[tid] = bias[tid];
        if (!ASPLIT) {
            // fused bn_finalize: affine from stats slot
            const float invN = 1.f / (float)N_NODESC;
            float mu  = stats_in[tid] * invN;
            float var = fmaf(-mu, mu, stats_in[CCH + tid] * invN);
            float rs  = rsqrtf(var + 1e-5f);
            float sc  = gg[tid] * rs;
            sSc[tid] = sc;
            sSh[tid] = fmaf(-mu, sc, bt[tid]);
        }
    }
    if (STATS && tid < 256) sStats[tid] = 0.f;
    __syncthreads();

    // ---- B tiles: straight bf16 copy from pre-split gmem ----
    {
        const uint4* bh4 = (const uint4*)Wh;
        const uint4* bl4 = (const uint4*)Wl;
#pragma unroll
        for (int i = 0; i < 8; i++) {
            int idx = tid + i * 256;        // 0..2047 uint4 units
            int row = idx >> 4;
            int c8  = idx & 15;
            *(uint4*)(sBh + row * PAD + c8 * 8) = bh4[idx];
            *(uint4*)(sBl + row * PAD + c8 * 8) = bl4[idx];
        }
    }
    // ---- A tiles ----
    if (ASPLIT) {
        // pure copy from pre-split gmem (scratch rows padded: no guard needed)
        const uint4* ah4 = (const uint4*)(Ahg + (size_t)m0 * CCH);
        const uint4* al4 = (const uint4*)(Alg + (size_t)m0 * CCH);
#pragma unroll
        for (int i = 0; i < 8; i++) {
            int idx = tid + i * 256;
            int row = idx >> 4;
            int c8  = idx & 15;
            *(uint4*)(sAh + row * PAD + c8 * 8) = ah4[idx];
            *(uint4*)(sAl + row * PAD + c8 * 8) = al4[idx];
        }
    } else {
        // fp32 load + BN affine + ReLU + fast split
        int r  = tid >> 1;            // 0..127
        int ch = (tid & 1) * 64;      // col half
        bool valid = (m0 + r) < M;
        const float* arow = A + (size_t)(m0 + r) * CCH + ch;
        uint32_t abase = (uint32_t)(r * PAD + ch);
#pragma unroll
        for (int q = 0; q < 64; q += 4) {
            float4 v = valid ? *(const float4*)(arow + q)
                             : make_float4(0.f, 0.f, 0.f, 0.f);
            int k = ch + q;
            v.x = fmaxf(fmaf(v.x, sSc[k + 0], sSh[k + 0]), 0.f);
            v.y = fmaxf(fmaf(v.y, sSc[k + 1], sSh[k + 1]), 0.f);
            v.z = fmaxf(fmaf(v.z, sSc[k + 2], sSh[k + 2]), 0.f);
            v.w = fmaxf(fmaf(v.w, sSc[k + 3], sSh[k + 3]), 0.f);
            uint2 hi, lo;
            fsplit2(v.x, v.y, hi.x, lo.x);
            fsplit2(v.z, v.w, hi.y, lo.y);
            *(uint2*)(sAh + abase + q) = hi;
            *(uint2*)(sAl + abase + q) = lo;
        }
    }
    __syncthreads();

    int a_row = (lane & 7) + ((lane >> 3) & 1) * 8;
    int a_k   = (lane >> 4) * 8;
    int b_row = lane & 7;
    int b_k   = ((lane >> 3) & 1) * 8;

    uint32_t uAh = smem_u32(sAh), uAl = smem_u32(sAl);
    uint32_t uBh = smem_u32(sBh), uBl = smem_u32(sBl);

    float acc[4][4][4];
#pragma unroll
    for (int i = 0; i < 4; i++)
#pragma unroll
        for (int j = 0; j < 4; j++)
#pragma unroll
            for (int q = 0; q < 4; q++) acc[i][j][q] = 0.f;

    for (int k0 = 0; k0 < CCH; k0 += 16) {
        uint32_t ah[4][4], al[4][4], bh[4][2], bl[4][2];
#pragma unroll
        for (int mt = 0; mt < 4; mt++) {
            uint32_t off = (uint32_t)(((wm * 64 + mt * 16 + a_row) * PAD + k0 + a_k) * 2);
            ldmx4(ah[mt], uAh + off);
            ldmx4(al[mt], uAl + off);
        }
#pragma unroll
        for (int nt = 0; nt < 4; nt++) {
            uint32_t off = (uint32_t)(((wn * 32 + nt * 8 + b_row) * PAD + k0 + b_k) * 2);
            ldmx2(bh[nt], uBh + off);
            ldmx2(bl[nt], uBl + off);
        }
#pragma unroll
        for (int mt = 0; mt < 4; mt++)
#pragma unroll
            for (int nt = 0; nt < 4; nt++) {
                mma16816(acc[mt][nt], ah[mt], bh[nt]);
                mma16816(acc[mt][nt], ah[mt], bl[nt]);
                mma16816(acc[mt][nt], al[mt], bh[nt]);
            }
    }

    // ---- epilogue ----
    float sums[4][2], sqs[4][2];
    if (STATS) {
#pragma unroll
        for (int nt = 0; nt < 4; nt++) {
            sums[nt][0] = sums[nt][1] = 0.f;
            sqs[nt][0] = sqs[nt][1] = 0.f;
        }
    }

#pragma unroll
    for (int nt = 0; nt < 4; nt++) {
        int col = wn * 32 + nt * 8 + (lane & 3) * 2;
        float b0 = sBias[col], b1 = sBias[col + 1];
#pragma unroll
        for (int mt = 0; mt < 4; mt++) {
#pragma unroll
            for (int hf = 0; hf < 2; hf++) {
                int m = m0 + wm * 64 + mt * 16 + (lane >> 2) + hf * 8;
                if (m < M) {
                    float v0 = acc[mt][nt][hf * 2 + 0] + b0;
                    float v1 = acc[mt][nt][hf * 2 + 1] + b1;
                    if (RELU) { v0 = fmaxf(v0, 0.f); v1 = fmaxf(v1, 0.f); }
                    if (!POOL)
                        *(float2*)(Cmat + (size_t)m * CCH + col) = make_float2(v0, v1);
                    if (STATS) {
                        sums[nt][0] += v0; sums[nt][1] += v1;
                        sqs[nt][0] = fmaf(v0, v0, sqs[nt][0]);
                        sqs[nt][1] = fmaf(v1, v1, sqs[nt][1]);
                    }
                    if (POOL) {
                        int b = __ldg(batch + m);
                        int* prow = (int*)&g_pool[(size_t)b * CCH + col];
                        atomicMax(prow,     __float_as_int(v0));
                        atomicMax(prow + 1, __float_as_int(v1));
                    }
                }
            }
        }
    }

    if (STATS) {
#pragma unroll
        for (int nt = 0; nt < 4; nt++) {
            int col = wn * 32 + nt * 8 + (lane & 3) * 2;
            atomicAdd(&sStats[col],           sums[nt][0]);
            atomicAdd(&sStats[col + 1],       sums[nt][1]);
            atomicAdd(&sStats[128 + col],     sqs[nt][0]);
            atomicAdd(&sStats[128 + col + 1], sqs[nt][1]);
        }
        __syncthreads();
        if (tid < 256) atomicAdd(&stats_out[tid], sStats[tid]);
    }
}

// ---------------- final linear [512,128] @ [5,128]^T + b --------------------
__global__ void final_linear_kernel(const float* __restrict__ lw,
                                    const float* __restrict__ lb,
                                    float* __restrict__ out) {
    int gph  = blockIdx.x;
    int o    = threadIdx.x >> 5;
    int lane = threadIdx.x & 31;
    const float* p    = g_pool + (size_t)gph * CCH;
    const float* wrow = lw + (size_t)o * CCH;
    float s = 0.f;
    for (int c = lane; c < CCH; c += 32) s = fmaf(p[c], wrow[c], s);
#pragma unroll
    for (int d = 16; d; d >>= 1) s += __shfl_xor_sync(0xffffffffu, s, d);
    if (lane == 0) out[gph * N_OUTC + o] = s + lb[o];
}

// ---------------- launch -----------------------------------------------------
extern "C" void kernel_launch(void* const* d_in, const int* in_sizes, int n_in,
                              void* d_out, int out_size) {
    const float* x   = (const float*)d_in[0];
    const int*   ei  = (const int*)  d_in[1];
    const float* ew  = (const float*)d_in[2];
    const int*   bat = (const int*)  d_in[3];
    const float* P[18];
    for (int i = 0; i < 18; i++) P[i] = (const float*)d_in[4 + i];
    // P: We0 be0 W1_0 b1_0 g0 bt0 W2_0 b2_0 | We1 be1 W1_1 b1_1 g1 bt1 W2_1 b2_1 | lin_w lin_b
    float* out = (float*)d_out;

    float *ph1, *pxo, *pst;
    __nv_bfloat16 *pwh, *pwl, *phh, *phl;
    cudaGetSymbolAddress((void**)&ph1, g_h1);
    cudaGetSymbolAddress((void**)&pxo, g_xo);
    cudaGetSymbolAddress((void**)&pst, g_stats);
    cudaGetSymbolAddress((void**)&pwh, g_wh);
    cudaGetSymbolAddress((void**)&pwl, g_wl);
    cudaGetSymbolAddress((void**)&phh, g_hh);
    cudaGetSymbolAddress((void**)&phl, g_hl);

    cudaFuncSetAttribute(gemm_mma_kernel<true, false, true, false>,
                         cudaFuncAttributeMaxDynamicSharedMemorySize, SMEM_GEMM);
    cudaFuncSetAttribute(gemm_mma_kernel<false, true, false, false>,
                         cudaFuncAttributeMaxDynamicSharedMemorySize, SMEM_GEMM);
    cudaFuncSetAttribute(gemm_mma_kernel<false, true, false, true>,
                         cudaFuncAttributeMaxDynamicSharedMemorySize, SMEM_GEMM);

    const int NBLK = (N_NODESC + 127) / 128;
    const int AGG_BLK = (N_NODESC + 7) / 8;

    setup_kernel<<<256, 256>>>(P[2], P[6], P[10], P[14]);
    bucket_build_kernel<<<(N_EDGESC + 255) / 256, 256>>>(ei, ew);

    const float* xin = x;
    for (int l = 0; l < 2; l++) {
        const float* We = P[l * 8 + 0];
        const float* be = P[l * 8 + 1];
        const float* b1 = P[l * 8 + 3];
        const float* gg = P[l * 8 + 4];
        const float* bt = P[l * 8 + 5];
        const float* b2 = P[l * 8 + 7];
        const __nv_bfloat16* W1h = pwh + (size_t)(l * 2 + 0) * CCH * CCH;
        const __nv_bfloat16* W1l = pwl + (size_t)(l * 2 + 0) * CCH * CCH;
        const __nv_bfloat16* W2h = pwh + (size_t)(l * 2 + 1) * CCH * CCH;
        const __nv_bfloat16* W2l = pwl + (size_t)(l * 2 + 1) * CCH * CCH;
        float* slot = pst + (size_t)l * 2 * CCH;

        // h (pre-split bf16 hi/lo) = x + aggregated messages
        node_agg_kernel<<<AGG_BLK, 256>>>(xin, We, be, phh, phl);
        // h1 = h @ W1^T + b1, fused BN stats -> slot (A pre-split: copy prologue)
        gemm_mma_kernel<true, false, true, false><<<NBLK, 256, SMEM_GEMM>>>(
            nullptr, phh, phl, W1h, W1l, b1, nullptr, nullptr, nullptr,
            slot, ph1, bat, N_NODESC);
        // x_out = relu( relu(BN(h1)) @ W2^T + b2 ), BN affine fused from slot
        if (l == 0) {
            gemm_mma_kernel<false, true, false, false><<<NBLK, 256, SMEM_GEMM>>>(
                ph1, nullptr, nullptr, W2h, W2l, b2, slot, gg, bt,
                nullptr, pxo, bat, N_NODESC);
        } else {
            gemm_mma_kernel<false, true, false, true><<<NBLK, 256, SMEM_GEMM>>>(
                ph1, nullptr, nullptr, W2h, W2l, b2, slot, gg, bt,
                nullptr, pxo, bat, N_NODESC);
        }
        xin = pxo;
    }

    final_linear_kernel<<<N_GRAPHS, 160>>>(P[16], P[17], out);
}

// round 10
// speedup vs baseline: 1.2412x; 1.1249x over previous
#include <cuda_runtime.h>
#include <cuda_bf16.h>
#include <math.h>
#include <stdint.h>

#define N_NODESC 50000
#define N_PADROW 50048   // 391 * 128
#define NT_TILES 391
#define GRID_P   148
#define N_EDGESC 800000
#define CCH      128
#define N_GRAPHS 512
#define N_OUTC   5
#define BKT_CAP  96
#define PAD      136       // bf16 elems per SMEM row
#define TILE_B   34816     // 128*PAD*2 bytes (one bf16 matrix tile)

// ---------------- scratch (device globals: allocation-free) ----------------
__device__ __align__(128) __nv_bfloat16 g_hh[N_PADROW * CCH];
__device__ __align__(128) __nv_bfloat16 g_hl[N_PADROW * CCH];
__device__ __align__(128) float g_h1[N_PADROW * CCH];
__device__ __align__(128) float g_xo[N_NODESC * CCH];
__device__ __align__(128) float g_stats [2 * 2 * CCH];
__device__ __align__(128) float g_pool[N_GRAPHS * CCH];
__device__ __align__(128) int   g_deg[N_NODESC];
__device__ __align__(128) int2  g_bucket[N_NODESC * BKT_CAP];
__device__ __align__(128) __nv_bfloat16 g_wh[4 * CCH * CCH];
__device__ __align__(128) __nv_bfloat16 g_wl[4 * CCH * CCH];
__device__ __align__(128) int   g_cnt[4];

// ---------------- PTX helpers ------------------------------------------------
__device__ __forceinline__ uint32_t smem_u32(const void* p) {
    uint32_t a;
    asm("{ .reg .u64 t; cvta.to.shared.u64 t, %1; cvt.u32.u64 %0, t; }"
        : "=r"(a) : "l"(p));
    return a;
}
__device__ __forceinline__ void ldmx4(uint32_t* r, uint32_t a) {
    asm volatile("ldmatrix.sync.aligned.m8n8.x4.shared.b16 {%0,%1,%2,%3}, [%4];"
                 : "=r"(r[0]), "=r"(r[1]), "=r"(r[2]), "=r"(r[3]) : "r"(a));
}
__device__ __forceinline__ void ldmx2(uint32_t* r, uint32_t a) {
    asm volatile("ldmatrix.sync.aligned.m8n8.x2.shared.b16 {%0,%1}, [%2];"
                 : "=r"(r[0]), "=r"(r[1]) : "r"(a));
}
__device__ __forceinline__ void mma16816(float* d, const uint32_t* a, const uint32_t* b) {
    asm volatile("mma.sync.aligned.m16n8k16.row.col.f32.bf16.bf16.f32 "
                 "{%0,%1,%2,%3}, {%4,%5,%6,%7}, {%8,%9}, {%0,%1,%2,%3};"
                 : "+f"(d[0]), "+f"(d[1]), "+f"(d[2]), "+f"(d[3])
                 : "r"(a[0]), "r"(a[1]), "r"(a[2]), "r"(a[3]), "r"(b[0]), "r"(b[1]));
}
#define CP_A16(dst, src) \
    asm volatile("cp.async.cg.shared.global [%0], [%1], 16;" \
                 :: "r"(dst), "l"(src) : "memory")
#define CP_COMMIT() asm volatile("cp.async.commit_group;" ::: "memory")
#define CP_WAIT0()  asm volatile("cp.async.wait_group 0;" ::: "memory")

__device__ __forceinline__ void fsplit2(float v0, float v1,
                                        uint32_t& hi, uint32_t& lo) {
    uint32_t u0 = __float_as_uint(v0), u1 = __float_as_uint(v1);
    hi = __byte_perm(u0, u1, 0x7632);
    float r0 = v0 - __uint_as_float(u0 & 0xFFFF0000u);
    float r1 = v1 - __uint_as_float(u1 & 0xFFFF0000u);
    lo = __byte_perm(__float_as_uint(r0), __float_as_uint(r1), 0x7632);
}

// ---------------- fused setup ------------------------------------------------
__global__ void setup_kernel(const float* __restrict__ Wa,
                             const float* __restrict__ Wb,
                             const float* __restrict__ Wc,
                             const float* __restrict__ Wd) {
    int i = blockIdx.x * 256 + threadIdx.x;       // 0..65535
    if (i < N_GRAPHS * CCH) g_pool[i] = 0.f;
    if (i < N_NODESC) g_deg[i] = 0;
    if (i < 4 * CCH) g_stats[i] = 0.f;
    if (i < 4) g_cnt[i] = 0;
    if (i < (N_PADROW - N_NODESC) * CCH) {        // zero pad rows
        size_t off = (size_t)N_NODESC * CCH + i;
        g_hh[off] = __float2bfloat16(0.f);
        g_hl[off] = __float2bfloat16(0.f);
        g_h1[off] = 0.f;
    }
    int w = i >> 14;
    int e = i & 16383;
    const float* src = (w == 0) ? Wa : (w == 1) ? Wb : (w == 2) ? Wc : Wd;
    float v = src[e];
    __nv_bfloat16 h = __float2bfloat16(v);
    __nv_bfloat16 l = __float2bfloat16(v - __bfloat162float(h));
    g_wh[i] = h;
    g_wl[i] = l;
}

// ---------------- bucket build ----------------------------------------------
__global__ void bucket_build_kernel(const int* __restrict__ ei,
                                    const float* __restrict__ ew) {
    int e = blockIdx.x * blockDim.x + threadIdx.x;
    if (e >= N_EDGESC) return;
    int s = ei[e];
    int d = ei[N_EDGESC + e];
    float w = ew[e];
    int p = atomicAdd(&g_deg[d], 1);
    g_bucket[(size_t)d * BKT_CAP + p] = make_int2(s, __float_as_int(w));
}

// ---------------- aggregation (writes pre-split bf16 hi/lo) -----------------
__global__ void __launch_bounds__(256)
node_agg_kernel(const float* __restrict__ x,
                const float* __restrict__ We,
                const float* __restrict__ be,
                __nv_bfloat16* __restrict__ hh,
                __nv_bfloat16* __restrict__ hl) {
    __shared__ float sWe[CCH];
    __shared__ float sbe[CCH];
    int t = threadIdx.x;
    if (t < CCH) sWe[t] = We[t];
    else         sbe[t - CCH] = be[t - CCH];
    __syncthreads();

    int warp = t >> 5;
    int lane = t & 31;
    int node = blockIdx.x * 8 + warp;
    if (node >= N_NODESC) return;

    int c = lane * 4;
    float w0 = sWe[c + 0], w1 = sWe[c + 1], w2 = sWe[c + 2], w3 = sWe[c + 3];
    float e0 = sbe[c + 0], e1 = sbe[c + 1], e2 = sbe[c + 2], e3 = sbe[c + 3];

    float4 acc = *(const float4*)(x + (size_t)node * CCH + c);
    float4 ac2 = make_float4(0.f, 0.f, 0.f, 0.f);

    int deg = __ldg(&g_deg[node]);
    const int2* bk = g_bucket + (size_t)node * BKT_CAP;

    int j = 0;
    for (; j + 2 <= deg; j += 2) {
        int2 p0 = __ldg(bk + j);
        int2 p1 = __ldg(bk + j + 1);
        float wa = __int_as_float(p0.y);
        float wb = __int_as_float(p1.y);
        float4 xa = *(const float4*)(x + (size_t)p0.x * CCH + c);
        float4 xb = *(const float4*)(x + (size_t)p1.x * CCH + c);
        acc.x += fmaxf(fmaf(wa, w0, xa.x) + e0, 0.f);
        ac2.x += fmaxf(fmaf(wb, w0, xb.x) + e0, 0.f);
        acc.y += fmaxf(fmaf(wa, w1, xa.y) + e1, 0.f);
        ac2.y += fmaxf(fmaf(wb, w1, xb.y) + e1, 0.f);
        acc.z += fmaxf(fmaf(wa, w2, xa.z) + e2, 0.f);
        ac2.z += fmaxf(fmaf(wb, w2, xb.z) + e2, 0.f);
        acc.w += fmaxf(fmaf(wa, w3, xa.w) + e3, 0.f);
        ac2.w += fmaxf(fmaf(wb, w3, xb.w) + e3, 0.f);
    }
    if (j < deg) {
        int2 p0 = __ldg(bk + j);
        float wa = __int_as_float(p0.y);
        float4 xa = *(const float4*)(x + (size_t)p0.x * CCH + c);
        acc.x += fmaxf(fmaf(wa, w0, xa.x) + e0, 0.f);
        acc.y += fmaxf(fmaf(wa, w1, xa.y) + e1, 0.f);
        acc.z += fmaxf(fmaf(wa, w2, xa.z) + e2, 0.f);
        acc.w += fmaxf(fmaf(wa, w3, xa.w) + e3, 0.f);
    }
    acc.x += ac2.x; acc.y += ac2.y; acc.z += ac2.z; acc.w += ac2.w;

    uint2 hi, lo;
    fsplit2(acc.x, acc.y, hi.x, lo.x);
    fsplit2(acc.z, acc.w, hi.y, lo.y);
    *(uint2*)(hh + (size_t)node * CCH + c) = hi;
    *(uint2*)(hl + (size_t)node * CCH + c) = lo;
}

// ================= persistent GEMM1: h1 = h @ W1^T + b1, fused BN stats =====
// A pre-split bf16 in gmem; double-buffered cp.async; dynamic tile counter.
static constexpr int SMEM_G1 = 2 * TILE_B + 4 * TILE_B + (128 + 256) * 4; // 210432

__global__ void __launch_bounds__(256, 1)
gemm1_kernel(const __nv_bfloat16* __restrict__ Ahg,
             const __nv_bfloat16* __restrict__ Alg,
             const __nv_bfloat16* __restrict__ Wh,
             const __nv_bfloat16* __restrict__ Wl,
             const float* __restrict__ bias,
             float* __restrict__ stats_out,
             float* __restrict__ Cmat,
             int* __restrict__ cnt) {
    extern __shared__ char smraw[];
    // layout: Bh, Bl, A[buf0]{h,l}, A[buf1]{h,l}, bias(128f), stats(256f)
    char* pB  = smraw;
    char* pA  = smraw + 2 * TILE_B;
    float* sBias  = (float*)(smraw + 6 * TILE_B);
    float* sStats = sBias + 128;
    __shared__ int sT[1];

    int tid  = threadIdx.x;
    int wid  = tid >> 5;
    int lane = tid & 31;
    int wm   = wid & 1;
    int wn   = wid >> 1;

    uint32_t uB = smem_u32(pB);
    uint32_t uA = smem_u32(pA);

    if (tid < 128) sBias[tid] = bias[tid];
    if (tid == 0) sT[0] = atomicAdd(cnt, 1);

    // B tiles once
#pragma unroll
    for (int i = 0; i < 8; i++) {
        int idx = tid + i * 256;
        int row = idx >> 4, c8 = idx & 15;
        uint32_t d = (uint32_t)((row * PAD + c8 * 8) * 2);
        CP_A16(uB + d,          (const char*)Wh + idx * 16);
        CP_A16(uB + TILE_B + d, (const char*)Wl + idx * 16);
    }
    __syncthreads();
    int t = sT[0];
    // first A tile -> buf0
    {
        size_t mb = (size_t)t * 128 * CCH * 2;   // byte offset
#pragma unroll
        for (int i = 0; i < 8; i++) {
            int idx = tid + i * 256;
            int row = idx >> 4, c8 = idx & 15;
            uint32_t d = (uint32_t)((row * PAD + c8 * 8) * 2);
            CP_A16(uA + d,          (const char*)Ahg + mb + idx * 16);
            CP_A16(uA + TILE_B + d, (const char*)Alg + mb + idx * 16);
        }
    }
    CP_COMMIT();
    CP_WAIT0();
    __syncthreads();

    int a_row = (lane & 7) + ((lane >> 3) & 1) * 8;
    int a_k   = (lane >> 4) * 8;
    int b_row = lane & 7;
    int b_k   = ((lane >> 3) & 1) * 8;

    // cross-tile register stats (column ownership tile-invariant)
    float sums[4][2], sqs[4][2];
#pragma unroll
    for (int nt = 0; nt < 4; nt++) {
        sums[nt][0] = sums[nt][1] = 0.f;
        sqs[nt][0] = sqs[nt][1] = 0.f;
    }

    int cur = 0;
    while (true) {
        if (tid == 0) sT[0] = atomicAdd(cnt, 1);
        __syncthreads();
        int nxt = sT[0];
        if (nxt < NT_TILES) {
            uint32_t ub = uA + (cur ^ 1) * (2 * TILE_B);
            size_t mb = (size_t)nxt * 128 * CCH * 2;
#pragma unroll
            for (int i = 0; i < 8; i++) {
                int idx = tid + i * 256;
                int row = idx >> 4, c8 = idx & 15;
                uint32_t d = (uint32_t)((row * PAD + c8 * 8) * 2);
                CP_A16(ub + d,          (const char*)Ahg + mb + idx * 16);
                CP_A16(ub + TILE_B + d, (const char*)Alg + mb + idx * 16);
            }
            CP_COMMIT();
        }

        // ---- mainloop ----
        uint32_t uAh = uA + cur * (2 * TILE_B);
        uint32_t uAl = uAh + TILE_B;
        uint32_t uBh = uB, uBl = uB + TILE_B;
        float acc[4][4][4];
#pragma unroll
        for (int i = 0; i < 4; i++)
#pragma unroll
            for (int j = 0; j < 4; j++)
#pragma unroll
                for (int q = 0; q < 4; q++) acc[i][j][q] = 0.f;

        for (int k0 = 0; k0 < CCH; k0 += 16) {
            uint32_t ah[4][4], al[4][4], bh[4][2], bl[4][2];
#pragma unroll
            for (int mt = 0; mt < 4; mt++) {
                uint32_t off = (uint32_t)(((wm * 64 + mt * 16 + a_row) * PAD + k0 + a_k) * 2);
                ldmx4(ah[mt], uAh + off);
                ldmx4(al[mt], uAl + off);
            }
#pragma unroll
            for (int nt = 0; nt < 4; nt++) {
                uint32_t off = (uint32_t)(((wn * 32 + nt * 8 + b_row) * PAD + k0 + b_k) * 2);
                ldmx2(bh[nt], uBh + off);
                ldmx2(bl[nt], uBl + off);
            }
#pragma unroll
            for (int mt = 0; mt < 4; mt++)
#pragma unroll
                for (int nt = 0; nt < 4; nt++) {
                    mma16816(acc[mt][nt], ah[mt], bh[nt]);
                    mma16816(acc[mt][nt], ah[mt], bl[nt]);
                    mma16816(acc[mt][nt], al[mt], bh[nt]);
                }
        }

        // ---- epilogue: store fp32 + accumulate stats in regs ----
        int m0 = t * 128;
#pragma unroll
        for (int nt = 0; nt < 4; nt++) {
            int col = wn * 32 + nt * 8 + (lane & 3) * 2;
            float b0 = sBias[col], b1 = sBias[col + 1];
#pragma unroll
            for (int mt = 0; mt < 4; mt++) {
#pragma unroll
                for (int hf = 0; hf < 2; hf++) {
                    int m = m0 + wm * 64 + mt * 16 + (lane >> 2) + hf * 8;
                    if (m < N_NODESC) {
                        float v0 = acc[mt][nt][hf * 2 + 0] + b0;
                        float v1 = acc[mt][nt][hf * 2 + 1] + b1;
                        *(float2*)(Cmat + (size_t)m * CCH + col) = make_float2(v0, v1);
                        sums[nt][0] += v0; sums[nt][1] += v1;
                        sqs[nt][0] = fmaf(v0, v0, sqs[nt][0]);
                        sqs[nt][1] = fmaf(v1, v1, sqs[nt][1]);
                    }
                }
            }
        }

        if (nxt >= NT_TILES) break;
        CP_WAIT0();
        __syncthreads();
        cur ^= 1;
        t = nxt;
    }

    // flush stats once
    if (tid < 256) sStats[tid] = 0.f;
    __syncthreads();
#pragma unroll
    for (int nt = 0; nt < 4; nt++) {
        int col = wn * 32 + nt * 8 + (lane & 3) * 2;
        atomicAdd(&sStats[col],           sums[nt][0]);
        atomicAdd(&sStats[col + 1],       sums[nt][1]);
        atomicAdd(&sStats[128 + col],     sqs[nt][0]);
        atomicAdd(&sStats[128 + col + 1], sqs[nt][1]);
    }
    __syncthreads();
    if (tid < 256) atomicAdd(&stats_out[tid], sStats[tid]);
}

// ====== persistent GEMM2: out = relu( relu(BN(h1)) @ W2^T + b2 ) ============
// fp32 A staged via cp.async, transform (affine+relu+split) SMEM->SMEM.
static constexpr int SMEM_G2 = 2 * TILE_B + 2 * TILE_B + 65536 + 3 * 128 * 4; // 206848

template <bool POOL>
__global__ void __launch_bounds__(256, 1)
gemm2_kernel(const float* __restrict__ A,
             const __nv_bfloat16* __restrict__ Wh,
             const __nv_bfloat16* __restrict__ Wl,
             const float* __restrict__ bias,
             const float* __restrict__ stats_in,
             const float* __restrict__ gg,
             const float* __restrict__ bt,
             float* __restrict__ Cmat,
             const int* __restrict__ batch,
             int* __restrict__ cnt) {
    extern __shared__ char smraw[];
    // layout: Bh, Bl, Ah, Al, staging(64KB fp32), bias/sc/sh (3*128f)
    char*  pB     = smraw;
    char*  pAh    = smraw + 2 * TILE_B;
    char*  pAl    = pAh + TILE_B;
    float* sStage = (float*)(smraw + 4 * TILE_B);
    float* sBias  = (float*)(smraw + 4 * TILE_B + 65536);
    float* sSc    = sBias + 128;
    float* sSh    = sSc + 128;
    __shared__ int sT[1];

    int tid  = threadIdx.x;
    int wid  = tid >> 5;
    int lane = tid & 31;
    int wm   = wid & 1;
    int wn   = wid >> 1;

    uint32_t uB  = smem_u32(pB);
    uint32_t uAh = smem_u32(pAh);
    uint32_t uAl = smem_u32(pAl);
    uint32_t uSt = smem_u32(sStage);

    if (tid < 128) {
        sBias[tid] = bias[tid];
        const float invN = 1.f / (float)N_NODESC;
        float mu  = stats_in[tid] * invN;
        float var = fmaf(-mu, mu, stats_in[CCH + tid] * invN);
        float rs  = rsqrtf(var + 1e-5f);
        float sc  = gg[tid] * rs;
        sSc[tid] = sc;
        sSh[tid] = fmaf(-mu, sc, bt[tid]);
    }
    if (tid == 0) sT[0] = atomicAdd(cnt, 1);

    // B tiles once
#pragma unroll
    for (int i = 0; i < 8; i++) {
        int idx = tid + i * 256;
        int row = idx >> 4, c8 = idx & 15;
        uint32_t d = (uint32_t)((row * PAD + c8 * 8) * 2);
        CP_A16(uB + d,          (const char*)Wh + idx * 16);
        CP_A16(uB + TILE_B + d, (const char*)Wl + idx * 16);
    }
    __syncthreads();
    int t = sT[0];
    // first A tile fp32 -> staging
    {
        size_t mb = (size_t)t * 128 * CCH * 4;
#pragma unroll
        for (int i = 0; i < 16; i++) {
            int idx = tid + i * 256;
            CP_A16(uSt + idx * 16, (const char*)A + mb + idx * 16);
        }
    }
    CP_COMMIT();
    CP_WAIT0();
    __syncthreads();

    int a_row = (lane & 7) + ((lane >> 3) & 1) * 8;
    int a_k   = (lane >> 4) * 8;
    int b_row = lane & 7;
    int b_k   = ((lane >> 3) & 1) * 8;

    // transform lambda-ish: staging -> Ah/Al with affine+relu+split
    auto transform = [&]() {
        int r  = tid >> 1;
        int ch = (tid & 1) * 64;
        const float* srow = sStage + r * CCH + ch;
        uint32_t abase = (uint32_t)((r * PAD + ch) * 2);
#pragma unroll
        for (int q = 0; q < 64; q += 4) {
            float4 v = *(const float4*)(srow + q);
            int k = ch + q;
            v.x = fmaxf(fmaf(v.x, sSc[k + 0], sSh[k + 0]), 0.f);
            v.y = fmaxf(fmaf(v.y, sSc[k + 1], sSh[k + 1]), 0.f);
            v.z = fmaxf(fmaf(v.z, sSc[k + 2], sSh[k + 2]), 0.f);
            v.w = fmaxf(fmaf(v.w, sSc[k + 3], sSh[k + 3]), 0.f);
            uint2 hi, lo;
            fsplit2(v.x, v.y, hi.x, lo.x);
            fsplit2(v.z, v.w, hi.y, lo.y);
            *(uint2*)((char*)pAh + abase + q * 2) = hi;
            *(uint2*)((char*)pAl + abase + q * 2) = lo;
        }
    };
    transform();
    __syncthreads();

    while (true) {
        if (tid == 0) sT[0] = atomicAdd(cnt, 1);
        __syncthreads();
        int nxt = sT[0];
        if (nxt < NT_TILES) {
            size_t mb = (size_t)nxt * 128 * CCH * 4;
#pragma unroll
            for (int i = 0; i < 16; i++) {
                int idx = tid + i * 256;
                CP_A16(uSt + idx * 16, (const char*)A + mb + idx * 16);
            }
            CP_COMMIT();
        }

        // ---- mainloop ----
        float acc[4][4][4];
#pragma unroll
        for (int i = 0; i < 4; i++)
#pragma unroll
            for (int j = 0; j < 4; j++)
#pragma unroll
                for (int q = 0; q < 4; q++) acc[i][j][q] = 0.f;

        for (int k0 = 0; k0 < CCH; k0 += 16) {
            uint32_t ah[4][4], al[4][4], bh[4][2], bl[4][2];
#pragma unroll
            for (int mt = 0; mt < 4; mt++) {
                uint32_t off = (uint32_t)(((wm * 64 + mt * 16 + a_row) * PAD + k0 + a_k) * 2);
                ldmx4(ah[mt], uAh + off);
                ldmx4(al[mt], uAl + off);
            }
#pragma unroll
            for (int nt = 0; nt < 4; nt++) {
                uint32_t off = (uint32_t)(((wn * 32 + nt * 8 + b_row) * PAD + k0 + b_k) * 2);
                ldmx2(bh[nt], uB + off);
                ldmx2(bl[nt], uB + TILE_B + off);
            }
#pragma unroll
            for (int mt = 0; mt < 4; mt++)
#pragma unroll
                for (int nt = 0; nt < 4; nt++) {
                    mma16816(acc[mt][nt], ah[mt], bh[nt]);
                    mma16816(acc[mt][nt], ah[mt], bl[nt]);
                    mma16816(acc[mt][nt], al[mt], bh[nt]);
                }
        }

        // ---- epilogue ----
        int m0 = t * 128;
#pragma unroll
        for (int nt = 0; nt < 4; nt++) {
            int col = wn * 32 + nt * 8 + (lane & 3) * 2;
            float b0 = sBias[col], b1 = sBias[col + 1];
#pragma unroll
            for (int mt = 0; mt < 4; mt++) {
#pragma unroll
                for (int hf = 0; hf < 2; hf++) {
                    int m = m0 + wm * 64 + mt * 16 + (lane >> 2) + hf * 8;
                    if (m < N_NODESC) {
                        float v0 = fmaxf(acc[mt][nt][hf * 2 + 0] + b0, 0.f);
                        float v1 = fmaxf(acc[mt][nt][hf * 2 + 1] + b1, 0.f);
                        if (POOL) {
                            int b = __ldg(batch + m);
                            int* prow = (int*)&g_pool[(size_t)b * CCH + col];
                            atomicMax(prow,     __float_as_int(v0));
                            atomicMax(prow + 1, __float_as_int(v1));
                        } else {
                            *(float2*)(Cmat + (size_t)m * CCH + col) = make_float2(v0, v1);
                        }
                    }
                }
            }
        }

        if (nxt >= NT_TILES) break;
        CP_WAIT0();
        __syncthreads();
        transform();
        __syncthreads();
        t = nxt;
    }
}

// ---------------- final linear ----------------------------------------------
__global__ void final_linear_kernel(const float* __restrict__ lw,
                                    const float* __restrict__ lb,
                                    float* __restrict__ out) {
    int gph  = blockIdx.x;
    int o    = threadIdx.x >> 5;
    int lane = threadIdx.x & 31;
    const float* p    = g_pool + (size_t)gph * CCH;
    const float* wrow = lw + (size_t)o * CCH;
    float s = 0.f;
    for (int c = lane; c < CCH; c += 32) s = fmaf(p[c], wrow[c], s);
#pragma unroll
    for (int d = 16; d; d >>= 1) s += __shfl_xor_sync(0xffffffffu, s, d);
    if (lane == 0) out[gph * N_OUTC + o] = s + lb[o];
}

// ---------------- launch -----------------------------------------------------
extern "C" void kernel_launch(void* const* d_in, const int* in_sizes, int n_in,
                              void* d_out, int out_size) {
    const float* x   = (const float*)d_in[0];
    const int*   ei  = (const int*)  d_in[1];
    const float* ew  = (const float*)d_in[2];
    const int*   bat = (const int*)  d_in[3];
    const float* P[18];
    for (int i = 0; i < 18; i++) P[i] = (const float*)d_in[4 + i];
    float* out = (float*)d_out;

    float *ph1, *pxo, *pst;
    __nv_bfloat16 *pwh, *pwl, *phh, *phl;
    int* pcnt;
    cudaGetSymbolAddress((void**)&ph1, g_h1);
    cudaGetSymbolAddress((void**)&pxo, g_xo);
    cudaGetSymbolAddress((void**)&pst, g_stats);
    cudaGetSymbolAddress((void**)&pwh, g_wh);
    cudaGetSymbolAddress((void**)&pwl, g_wl);
    cudaGetSymbolAddress((void**)&phh, g_hh);
    cudaGetSymbolAddress((void**)&phl, g_hl);
    cudaGetSymbolAddress((void**)&pcnt, g_cnt);

    cudaFuncSetAttribute(gemm1_kernel,
                         cudaFuncAttributeMaxDynamicSharedMemorySize, SMEM_G1);
    cudaFuncSetAttribute(gemm2_kernel<false>,
                         cudaFuncAttributeMaxDynamicSharedMemorySize, SMEM_G2);
    cudaFuncSetAttribute(gemm2_kernel<true>,
                         cudaFuncAttributeMaxDynamicSharedMemorySize, SMEM_G2);

    const int AGG_BLK = (N_NODESC + 7) / 8;

    setup_kernel<<<256, 256>>>(P[2], P[6], P[10], P[14]);
    bucket_build_kernel<<<(N_EDGESC + 255) / 256, 256>>>(ei, ew);

    const float* xin = x;
    for (int l = 0; l < 2; l++) {
        const float* We = P[l * 8 + 0];
        const float* be = P[l * 8 + 1];
        const float* b1 = P[l * 8 + 3];
        const float* gg = P[l * 8 + 4];
        const float* bt = P[l * 8 + 5];
        const float* b2 = P[l * 8 + 7];
        const __nv_bfloat16* W1h = pwh + (size_t)(l * 2 + 0) * CCH * CCH;
        const __nv_bfloat16* W1l = pwl + (size_t)(l * 2 + 0) * CCH * CCH;
        const __nv_bfloat16* W2h = pwh + (size_t)(l * 2 + 1) * CCH * CCH;
        const __nv_bfloat16* W2l = pwl + (size_t)(l * 2 + 1) * CCH * CCH;
        float* slot = pst + (size_t)l * 2 * CCH;

        node_agg_kernel<<<AGG_BLK, 256>>>(xin, We, be, phh, phl);
        gemm1_kernel<<<GRID_P, 256, SMEM_G1>>>(
            phh, phl, W1h, W1l, b1, slot, ph1, pcnt + l * 2);
        if (l == 0) {
            gemm2_kernel<false><<<GRID_P, 256, SMEM_G2>>>(
                ph1, W2h, W2l, b2, slot, gg, bt, pxo, bat, pcnt + l * 2 + 1);
        } else {
            gemm2_kernel<true><<<GRID_P, 256, SMEM_G2>>>(
                ph1, W2h, W2l, b2, slot, gg, bt, pxo, bat, pcnt + l * 2 + 1);
        }
        xin = pxo;
    }

    final_linear_kernel<<<N_GRAPHS, 160>>>(P[16], P[17], out);
}